// round 11
// baseline (speedup 1.0000x reference)
#include <cuda_runtime.h>
#include <cuda_fp16.h>
#include <math.h>
#include <stdint.h>

#define L_   1024
#define D_   512
#define H_   8
#define HD_  64
#define KF_  24
#define EPSF 1e-5f
#define NCH  32
#define CL   32

// ---------------- static scratch ----------------
__device__ float g_q[L_ * D_];
__device__ float g_k[L_ * D_];
__device__ float g_v[L_ * D_];
__device__ __half g_ckh[(size_t)KF_ * L_ * D_];   // conv(k_norm) fp16: [kf][l][c]
__device__ __half g_cvh[(size_t)KF_ * L_ * D_];   // conv(v_norm) fp16
__device__ float g_sim[H_ * L_];
__device__ float g_gate[H_ * L_];
__device__ float g_coef[H_ * L_];
__device__ float g_ctxt[L_ * D_];
__device__ float g_T[H_][NCH][4096];
__device__ float g_P[H_][NCH][4096];

// fp16 operands
__device__ __half g_uTh[1024 * 1024];            // u, [c (k:0-511, v:512-1023)][t]
__device__ __half g_fpad[2 * KF_ * 2048];        // filters [hi/lo][kf][1023 + lag]
__device__ __half g_xh[L_ * D_], g_xl[L_ * D_];  // x splits [m][k]
__device__ __half g_ch[L_ * D_], g_cl[L_ * D_];  // ctxt splits [m][k]
__device__ __half g_WTh[4 * D_ * D_], g_WTl[4 * D_ * D_]; // W^T splits [mat][n][k]

// ---------------- mma.sync fp16 ----------------
__device__ __forceinline__ void mma16816(float* c, const uint32_t* a, const uint32_t* b) {
    asm volatile(
        "mma.sync.aligned.m16n8k16.row.col.f32.f16.f16.f32 "
        "{%0,%1,%2,%3}, {%4,%5,%6,%7}, {%8,%9}, {%0,%1,%2,%3};"
        : "+f"(c[0]), "+f"(c[1]), "+f"(c[2]), "+f"(c[3])
        : "r"(a[0]), "r"(a[1]), "r"(a[2]), "r"(a[3]), "r"(b[0]), "r"(b[1]));
}

__device__ __forceinline__ void cp_async16(uint32_t saddr, const void* gptr) {
    asm volatile("cp.async.cg.shared.global [%0], [%1], 16;" :: "r"(saddr), "l"(gptr));
}
#define CP_COMMIT() asm volatile("cp.async.commit_group;" ::: "memory")
#define CP_WAIT0()  asm volatile("cp.async.wait_group 0;" ::: "memory")

// ---------------- prep: W transpose + fp16 split  WT[z][n][k] = split(W[k][n]) ----------------
__global__ void prep_wT_kernel(const float* __restrict__ w0, const float* __restrict__ w1,
                               const float* __restrict__ w2, const float* __restrict__ w3) {
    __shared__ float tile[32][33];
    const int k0 = blockIdx.x * 32, n0 = blockIdx.y * 32, z = blockIdx.z;
    const float* __restrict__ src = (z == 0) ? w0 : (z == 1) ? w1 : (z == 2) ? w2 : w3;
    const int tx = threadIdx.x, ty = threadIdx.y;
    #pragma unroll
    for (int kk = 0; kk < 4; kk++) {
        int i = ty + 8 * kk;
        tile[i][tx] = src[(k0 + i) * 512 + n0 + tx];
    }
    __syncthreads();
    const size_t zb = (size_t)z * (D_ * D_);
    #pragma unroll
    for (int kk = 0; kk < 4; kk++) {
        int i = ty + 8 * kk;
        float v = tile[tx][i];                     // = W[k0+tx][n0+i]
        __half hi = __float2half_rn(v);
        __half lo = __float2half_rn(v - __half2float(hi));
        size_t idx = zb + (size_t)(n0 + i) * 512 + k0 + tx;
        g_WTh[idx] = hi;
        g_WTl[idx] = lo;
    }
}

// ---------------- prep: elementwise fp32 -> fp16 hi/lo split ----------------
__global__ void split_f32_kernel(const float* __restrict__ src,
                                 __half* __restrict__ dh, __half* __restrict__ dl) {
    int i = blockIdx.x * 1024 + threadIdx.x;
    if (i < L_ * D_) {
        float v = src[i];
        __half hi = __float2half_rn(v);
        dh[i] = hi;
        dl[i] = __float2half_rn(v - __half2float(hi));
    }
}

// ---------------- HMMA projection GEMM: C[1024x512] = A[1024x512] @ W[512x512] + bias ----------------
// 3-product fp16 split. Block 128m x 128n, 8 warps (warp 32x64), K-chunks of 32.
#define GS 40
__global__ void __launch_bounds__(256) hmma_gemm_kernel(
    const __half* __restrict__ Ah, const __half* __restrict__ Al,
    const __half* __restrict__ WTh, const __half* __restrict__ WTl,
    const float* __restrict__ b0, const float* __restrict__ b1, const float* __restrict__ b2,
    float* C0, float* C1, float* C2) {
    __shared__ __align__(16) __half SA[2][128][GS];
    __shared__ __align__(16) __half SB[2][128][GS];

    const int tid = threadIdx.x;
    const int wid = tid >> 5, lane = tid & 31;
    const int g = lane >> 2, tg = lane & 3;
    const int wm = (wid & 3) * 32, wn = (wid >> 2) * 64;
    const int n0 = blockIdx.x * 128, m0 = blockIdx.y * 128, z = blockIdx.z;

    const __half* __restrict__ Bh = WTh + (size_t)z * (D_ * D_);
    const __half* __restrict__ Bl = WTl + (size_t)z * (D_ * D_);
    const float* __restrict__ bias = (z == 0) ? b0 : (z == 1) ? b1 : b2;
    float* __restrict__ C = (z == 0) ? C0 : (z == 1) ? C1 : C2;

    float acc[2][8][4] = {};

    for (int k0 = 0; k0 < 512; k0 += 32) {
        #pragma unroll
        for (int r = 0; r < 8; r++) {
            int idx = tid + 256 * r;              // 2048 chunks of 16B
            int which = idx >> 10;
            int split = (idx >> 9) & 1;
            int rem = idx & 511;
            int row = rem >> 2, qq = rem & 3;
            const __half* src = which
                ? (split ? Bl : Bh) + (size_t)(n0 + row) * 512 + k0 + qq * 8
                : (split ? Al : Ah) + (size_t)(m0 + row) * 512 + k0 + qq * 8;
            __half* dst = which ? &SB[split][row][qq * 8] : &SA[split][row][qq * 8];
            cp_async16((uint32_t)__cvta_generic_to_shared(dst), src);
        }
        CP_COMMIT();
        CP_WAIT0();
        __syncthreads();

        #pragma unroll
        for (int ks = 0; ks < 2; ks++) {
            const int kb = ks * 16 + tg * 2;
            uint32_t ah[2][4], al2[2][4];
            #pragma unroll
            for (int i = 0; i < 2; i++) {
                int r = wm + i * 16 + g;
                ah[i][0] = *(const uint32_t*)&SA[0][r][kb];
                ah[i][1] = *(const uint32_t*)&SA[0][r + 8][kb];
                ah[i][2] = *(const uint32_t*)&SA[0][r][kb + 8];
                ah[i][3] = *(const uint32_t*)&SA[0][r + 8][kb + 8];
                al2[i][0] = *(const uint32_t*)&SA[1][r][kb];
                al2[i][1] = *(const uint32_t*)&SA[1][r + 8][kb];
                al2[i][2] = *(const uint32_t*)&SA[1][r][kb + 8];
                al2[i][3] = *(const uint32_t*)&SA[1][r + 8][kb + 8];
            }
            #pragma unroll
            for (int j = 0; j < 8; j++) {
                int cc = wn + j * 8 + g;
                uint32_t bh[2], bl[2];
                bh[0] = *(const uint32_t*)&SB[0][cc][kb];
                bh[1] = *(const uint32_t*)&SB[0][cc][kb + 8];
                bl[0] = *(const uint32_t*)&SB[1][cc][kb];
                bl[1] = *(const uint32_t*)&SB[1][cc][kb + 8];
                #pragma unroll
                for (int i = 0; i < 2; i++) {
                    mma16816(acc[i][j], ah[i], bh);
                    mma16816(acc[i][j], al2[i], bh);
                    mma16816(acc[i][j], ah[i], bl);
                }
            }
        }
        __syncthreads();
    }

    #pragma unroll
    for (int i = 0; i < 2; i++) {
        int r = m0 + wm + i * 16 + g;
        #pragma unroll
        for (int j = 0; j < 8; j++) {
            int cc = n0 + wn + j * 8 + tg * 2;
            float bv0 = bias[cc], bv1 = bias[cc + 1];
            *(float2*)(C + (size_t)r * 512 + cc) = make_float2(acc[i][j][0] + bv0, acc[i][j][1] + bv1);
            *(float2*)(C + (size_t)(r + 8) * 512 + cc) = make_float2(acc[i][j][2] + bv0, acc[i][j][3] + bv1);
        }
    }
}

// ---------------- sim + in-place L2 norm ----------------
__global__ void norm_sim_kernel(const float* __restrict__ qk_scale) {
    const int l = blockIdx.x;
    const int c = threadIdx.x;
    const int head = c >> 6, d = c & 63;
    float q = g_q[l * 512 + c];
    float k = g_k[l * 512 + c];
    float v = g_v[l * 512 + c];

    __shared__ float sd[512], sk[512], sv[512];
    sd[c] = q * k; sk[c] = k * k; sv[c] = v * v;
    __syncthreads();
    for (int off = 32; off >= 1; off >>= 1) {
        if (d < off) {
            sd[c] += sd[c + off];
            sk[c] += sk[c + off];
            sv[c] += sv[c + off];
        }
        __syncthreads();
    }
    float nk = fmaxf(sqrtf(sk[head * 64]), 1e-12f);
    float nv = fmaxf(sqrtf(sv[head * 64]), 1e-12f);
    g_k[l * 512 + c] = k / nk;
    g_v[l * 512 + c] = v / nv;
    if (d == 0) g_sim[head * L_ + l] = sd[head * 64] * qk_scale[head];
}

// ---------------- prep: transpose + fp16 convert of normalized k,v ----------------
__global__ void prep_split_kernel() {
    __shared__ float tile[32][33];
    const int t0 = blockIdx.x * 32, c0 = blockIdx.y * 32, z = blockIdx.z;
    const float* __restrict__ src = z ? g_v : g_k;
    const int tx = threadIdx.x, ty = threadIdx.y;
    #pragma unroll
    for (int kk = 0; kk < 4; kk++) {
        int i = ty + 8 * kk;
        tile[i][tx] = src[(t0 + i) * 512 + c0 + tx];
    }
    __syncthreads();
    const int rb = z * 512;
    #pragma unroll
    for (int kk = 0; kk < 4; kk++) {
        int i = ty + 8 * kk;
        g_uTh[(size_t)(rb + c0 + i) * 1024 + t0 + tx] = __float2half_rn(tile[tx][i]);
    }
}

// ---------------- prep: padded filters fp16 hi/lo ----------------
__global__ void prep_filters_kernel(const float* __restrict__ flt) {
    int idx = blockIdx.x * 1024 + threadIdx.x;
    if (idx >= KF_ * 2048) return;
    int kf = idx >> 11, d = idx & 2047;
    float v = 0.0f;
    if (d >= 1023 && d < 2047) v = flt[(d - 1023) * KF_ + kf];
    __half hi = __float2half_rn(v);
    __half lo = __float2half_rn(v - __half2float(hi));
    g_fpad[idx] = hi;
    g_fpad[KF_ * 2048 + idx] = lo;
}

// ---------------- HMMA conv (fp16 2-term), fp16 output ----------------
#define BS_STRIDE 40

__global__ void __launch_bounds__(256) conv_mma_kernel() {
    __shared__ __align__(16) __half Bs[2][128][BS_STRIDE];
    __shared__ uint32_t fwp[2][2][160];

    const int tid = threadIdx.x;
    const int wid = tid >> 5, lane = tid & 31;
    const int g = lane >> 2, tg = lane & 3;
    const int wm = (wid & 3) * 32;
    const int wn = (wid >> 2) * 64;

    const int c0 = blockIdx.x * 128;
    const int l0 = (7 - blockIdx.y) * 128;
    const int kf = blockIdx.z;

    const __half* __restrict__ fp_hi = g_fpad + (size_t)kf * 2048;
    const __half* __restrict__ fp_lo = g_fpad + (size_t)(KF_ + kf) * 2048;

    const int nIter = (l0 + 128) >> 5;

    auto prefetch = [&](int it, int buf) {
        const int t0 = it << 5;
        #pragma unroll
        for (int r = 0; r < 2; r++) {
            int cidx = tid + 256 * r;
            int c = cidx >> 2, qq = cidx & 3;
            const __half* gsrc = g_uTh + (size_t)(c0 + c) * 1024 + t0 + qq * 8;
            cp_async16((uint32_t)__cvta_generic_to_shared(&Bs[buf][c][qq * 8]), gsrc);
        }
        CP_COMMIT();
        if (tid < 160) {
            int dmin = 1023 + (l0 - t0) - 31;
            uint32_t h0 = (uint32_t)__half_as_ushort(fp_hi[dmin + tid]);
            uint32_t h1 = (uint32_t)__half_as_ushort(fp_hi[dmin + tid - 1]);
            fwp[buf][0][tid] = h0 | (h1 << 16);
            uint32_t lo0 = (uint32_t)__half_as_ushort(fp_lo[dmin + tid]);
            uint32_t lo1 = (uint32_t)__half_as_ushort(fp_lo[dmin + tid - 1]);
            fwp[buf][1][tid] = lo0 | (lo1 << 16);
        }
    };

    float acc[2][8][4] = {};

    prefetch(0, 0);
    CP_WAIT0();
    __syncthreads();

    for (int it = 0; it < nIter; it++) {
        const int buf = it & 1;
        if (it + 1 < nIter) prefetch(it + 1, buf ^ 1);

        #pragma unroll
        for (int ks = 0; ks < 2; ks++) {
            const int kb = ks * 16;
            uint32_t a0[2][2], a1[2][2], a2[2][2];
            #pragma unroll
            for (int s = 0; s < 2; s++)
                #pragma unroll
                for (int i = 0; i < 2; i++) {
                    int x = wm + i * 16 + g - (kb + tg * 2) + 31;
                    a0[s][i] = fwp[buf][s][x];
                    a1[s][i] = fwp[buf][s][x + 8];
                    a2[s][i] = fwp[buf][s][x - 8];
                }
            #pragma unroll
            for (int j = 0; j < 8; j++) {
                int cc = wn + j * 8 + g;
                uint32_t bh[2];
                bh[0] = *(const uint32_t*)&Bs[buf][cc][kb + tg * 2];
                bh[1] = *(const uint32_t*)&Bs[buf][cc][kb + tg * 2 + 8];
                #pragma unroll
                for (int i = 0; i < 2; i++) {
                    uint32_t ah[4] = {a0[0][i], a1[0][i], a2[0][i], a0[0][i]};
                    uint32_t al[4] = {a0[1][i], a1[1][i], a2[1][i], a0[1][i]};
                    mma16816(acc[i][j], ah, bh);
                    mma16816(acc[i][j], al, bh);
                }
            }
        }
        if (it + 1 < nIter) CP_WAIT0();
        __syncthreads();
    }

    __half* __restrict__ base = (c0 < 512) ? g_ckh : g_cvh;
    const int cb0 = (c0 < 512) ? c0 : c0 - 512;
    #pragma unroll
    for (int i = 0; i < 2; i++) {
        int r = l0 + wm + i * 16 + g;
        #pragma unroll
        for (int j = 0; j < 8; j++) {
            int cc = cb0 + wn + j * 8 + tg * 2;
            size_t o0 = ((size_t)kf * 1024 + r) * 512 + cc;
            size_t o1 = ((size_t)kf * 1024 + r + 8) * 512 + cc;
            *(__half2*)(base + o0) = __floats2half2_rn(acc[i][j][0], acc[i][j][1]);
            *(__half2*)(base + o1) = __floats2half2_rn(acc[i][j][2], acc[i][j][3]);
        }
    }
}

// ---------------- Pass A: per-chunk gated-Z totals + gates ----------------
__global__ void __launch_bounds__(256) zsum_kernel(const float* __restrict__ Wg,
                                                   const float* __restrict__ bg,
                                                   const float* __restrict__ kvscale) {
    const int chunk = blockIdx.x, head = blockIdx.y;
    const int tid = threadIdx.x;
    const int e = tid & 63, dg = tid >> 6;
    const int l0 = chunk * CL;

    __shared__ __align__(16) __half st[2][48][64];   // rows 0..23 ck, 24..47 cv
    __shared__ float red[8];
    __shared__ float gsh;

    float scl[16], wg[16];
    #pragma unroll
    for (int r = 0; r < 16; r++) {
        int m = (dg * 16 + r) * 64 + e;
        scl[r] = kvscale[head * 4096 + m];
        wg[r] = Wg[m];
    }
    const float bgv = bg[0];

    auto stage = [&](int l, int buf) {
        for (int i = tid; i < 384; i += 256) {
            int row = i >> 3, ch = i & 7;
            const __half* src = ((row < 24) ? (g_ckh + (size_t)row * (L_ * D_))
                                            : (g_cvh + (size_t)(row - 24) * (L_ * D_)))
                                + (size_t)l * 512 + head * 64 + ch * 8;
            cp_async16((uint32_t)__cvta_generic_to_shared(&st[buf][row][ch * 8]), src);
        }
        CP_COMMIT();
    };

    float S[16] = {};
    stage(l0, 0);

    for (int li = 0; li < CL; li++) {
        const int buf = li & 1;
        CP_WAIT0();
        __syncthreads();
        if (li + 1 < CL) stage(l0 + li + 1, buf ^ 1);

        float z[16] = {};
        #pragma unroll
        for (int kf = 0; kf < KF_; kf++) {
            float ktv = __half2float(st[buf][kf][e]);
            const __half2* vp = (const __half2*)&st[buf][24 + kf][dg * 16];
            float2 p0 = __half22float2(vp[0]), p1 = __half22float2(vp[1]);
            float2 p2 = __half22float2(vp[2]), p3 = __half22float2(vp[3]);
            float2 p4 = __half22float2(vp[4]), p5 = __half22float2(vp[5]);
            float2 p6 = __half22float2(vp[6]), p7 = __half22float2(vp[7]);
            z[0] += p0.x * ktv;  z[1] += p0.y * ktv;  z[2] += p1.x * ktv;  z[3] += p1.y * ktv;
            z[4] += p2.x * ktv;  z[5] += p2.y * ktv;  z[6] += p3.x * ktv;  z[7] += p3.y * ktv;
            z[8] += p4.x * ktv;  z[9] += p4.y * ktv;  z[10] += p5.x * ktv; z[11] += p5.y * ktv;
            z[12] += p6.x * ktv; z[13] += p6.y * ktv; z[14] += p7.x * ktv; z[15] += p7.y * ktv;
        }
        float lp = 0.0f;
        #pragma unroll
        for (int r = 0; r < 16; r++) {
            z[r] *= scl[r];
            lp += z[r] * wg[r];
        }
        #pragma unroll
        for (int off = 16; off >= 1; off >>= 1)
            lp += __shfl_xor_sync(0xffffffffu, lp, off);
        if ((tid & 31) == 0) red[tid >> 5] = lp;
        __syncthreads();
        if (tid == 0) {
            float s = red[0] + red[1] + red[2] + red[3] + red[4] + red[5] + red[6] + red[7];
            float rl = fmaxf(s + bgv, 0.0f);
            float gate = rl * rl + EPSF;
            gsh = gate;
            g_gate[head * L_ + l0 + li] = gate;
        }
        __syncthreads();
        float gate = gsh;
        #pragma unroll
        for (int r = 0; r < 16; r++) S[r] += gate * z[r];
    }

    #pragma unroll
    for (int r = 0; r < 16; r++)
        g_T[head][chunk][(dg * 16 + r) * 64 + e] = S[r];
}

// ---------------- Pass B: exclusive chunk prefix ----------------
__global__ void chunk_prefix_kernel() {
    const int head = blockIdx.y;
    const int comp = blockIdx.x * 256 + threadIdx.x;
    float run = 0.0f;
    #pragma unroll
    for (int ch = 0; ch < NCH; ch++) {
        float t = g_T[head][ch][comp];
        g_P[head][ch][comp] = run;
        run += t;
    }
}

// ---------------- coef: online softmax scan + gate cumsum ----------------
__global__ void coef_kernel() {
    const int head = blockIdx.x;
    const int i = threadIdx.x;
    __shared__ float sm[1024], ss[1024], sg[1024];
    float si = g_sim[head * L_ + i];
    sm[i] = si; ss[i] = 1.0f; sg[i] = g_gate[head * L_ + i];
    __syncthreads();
    for (int off = 1; off < 1024; off <<= 1) {
        float mp = 0.f, sp = 0.f, gp = 0.f;
        bool has = (i >= off);
        if (has) { mp = sm[i - off]; sp = ss[i - off]; gp = sg[i - off]; }
        __syncthreads();
        if (has) {
            float mi = sm[i], s_i = ss[i];
            float mn = fmaxf(mp, mi);
            ss[i] = sp * __expf(mp - mn) + s_i * __expf(mi - mn);
            sm[i] = mn;
            sg[i] += gp;
        }
        __syncthreads();
    }
    float w = __expf(si - sm[i]) / (ss[i] + EPSF);
    float silu = w / (1.0f + __expf(-w));
    g_coef[head * L_ + i] = (1.0f + silu) / (sg[i] + EPSF);
}

// ---------------- Pass C: running scan + q contraction -> ctxt ----------------
__global__ void __launch_bounds__(256) ctxt_scan_kernel(const float* __restrict__ kvscale) {
    const int chunk = blockIdx.x, head = blockIdx.y;
    const int tid = threadIdx.x;
    const int e = tid & 63, dg = tid >> 6;
    const int l0 = chunk * CL;

    __shared__ __align__(16) __half st[2][48][64];
    __shared__ __align__(16) float sq[2][64];
    __shared__ float red4[4][64];
    __shared__ float gt[CL], cf[CL];

    float scl[16];
    #pragma unroll
    for (int r = 0; r < 16; r++)
        scl[r] = kvscale[head * 4096 + (dg * 16 + r) * 64 + e];

    if (tid < CL) {
        gt[tid] = g_gate[head * L_ + l0 + tid];
        cf[tid] = g_coef[head * L_ + l0 + tid];
    }

    float S[16];
    #pragma unroll
    for (int r = 0; r < 16; r++)
        S[r] = g_P[head][chunk][(dg * 16 + r) * 64 + e];

    auto stage = [&](int l, int buf) {
        for (int i = tid; i < 400; i += 256) {
            if (i < 384) {
                int row = i >> 3, ch = i & 7;
                const __half* src = ((row < 24) ? (g_ckh + (size_t)row * (L_ * D_))
                                                : (g_cvh + (size_t)(row - 24) * (L_ * D_)))
                                    + (size_t)l * 512 + head * 64 + ch * 8;
                cp_async16((uint32_t)__cvta_generic_to_shared(&st[buf][row][ch * 8]), src);
            } else {
                int qi = i - 384;
                const float* src = g_q + (size_t)l * 512 + head * 64 + qi * 4;
                cp_async16((uint32_t)__cvta_generic_to_shared(&sq[buf][qi * 4]), src);
            }
        }
        CP_COMMIT();
    };

    stage(l0, 0);

    for (int li = 0; li < CL; li++) {
        const int buf = li & 1;
        CP_WAIT0();
        __syncthreads();
        if (li + 1 < CL) stage(l0 + li + 1, buf ^ 1);

        float z[16] = {};
        #pragma unroll
        for (int kf = 0; kf < KF_; kf++) {
            float ktv = __half2float(st[buf][kf][e]);
            const __half2* vp = (const __half2*)&st[buf][24 + kf][dg * 16];
            float2 p0 = __half22float2(vp[0]), p1 = __half22float2(vp[1]);
            float2 p2 = __half22float2(vp[2]), p3 = __half22float2(vp[3]);
            float2 p4 = __half22float2(vp[4]), p5 = __half22float2(vp[5]);
            float2 p6 = __half22float2(vp[6]), p7 = __half22float2(vp[7]);
            z[0] += p0.x * ktv;  z[1] += p0.y * ktv;  z[2] += p1.x * ktv;  z[3] += p1.y * ktv;
            z[4] += p2.x * ktv;  z[5] += p2.y * ktv;  z[6] += p3.x * ktv;  z[7] += p3.y * ktv;
            z[8] += p4.x * ktv;  z[9] += p4.y * ktv;  z[10] += p5.x * ktv; z[11] += p5.y * ktv;
            z[12] += p6.x * ktv; z[13] += p6.y * ktv; z[14] += p7.x * ktv; z[15] += p7.y * ktv;
        }
        const float gate = gt[li];
        #pragma unroll
        for (int r = 0; r < 16; r++) S[r] += gate * scl[r] * z[r];

        const float4* qp = (const float4*)&sq[buf][dg * 16];
        float4 q0 = qp[0], q1 = qp[1], q2 = qp[2], q3 = qp[3];
        float part =
            q0.x * S[0]  + q0.y * S[1]  + q0.z * S[2]  + q0.w * S[3] +
            q1.x * S[4]  + q1.y * S[5]  + q1.z * S[6]  + q1.w * S[7] +
            q2.x * S[8]  + q2.y * S[9]  + q2.z * S[10] + q2.w * S[11] +
            q3.x * S[12] + q3.y * S[13] + q3.z * S[14] + q3.w * S[15];
        red4[dg][e] = part;
        __syncthreads();
        if (dg == 0) {
            float o = (red4[0][e] + red4[1][e] + red4[2][e] + red4[3][e]) * cf[li];
            g_ctxt[(size_t)(l0 + li) * 512 + head * 64 + e] = o;
        }
    }
}

// ---------------- launch ----------------
extern "C" void kernel_launch(void* const* d_in, const int* in_sizes, int n_in,
                              void* d_out, int out_size) {
    const float* x   = (const float*)d_in[0];
    const float* Wq  = (const float*)d_in[1];
    const float* bq  = (const float*)d_in[2];
    const float* Wk  = (const float*)d_in[3];
    const float* bk  = (const float*)d_in[4];
    const float* Wv  = (const float*)d_in[5];
    const float* bv  = (const float*)d_in[6];
    const float* Wo  = (const float*)d_in[7];
    const float* bo  = (const float*)d_in[8];
    const float* Wg  = (const float*)d_in[9];
    const float* bg  = (const float*)d_in[10];
    const float* kvs = (const float*)d_in[11];
    const float* qks = (const float*)d_in[12];
    const float* flt = (const float*)d_in[13];
    float* out = (float*)d_out;

    void *pq, *pk, *pv, *pctxt, *pxh, *pxl, *pch, *pcl, *pwth, *pwtl;
    cudaGetSymbolAddress(&pq, g_q);
    cudaGetSymbolAddress(&pk, g_k);
    cudaGetSymbolAddress(&pv, g_v);
    cudaGetSymbolAddress(&pctxt, g_ctxt);
    cudaGetSymbolAddress(&pxh, g_xh);
    cudaGetSymbolAddress(&pxl, g_xl);
    cudaGetSymbolAddress(&pch, g_ch);
    cudaGetSymbolAddress(&pcl, g_cl);
    cudaGetSymbolAddress(&pwth, g_WTh);
    cudaGetSymbolAddress(&pwtl, g_WTl);

    prep_wT_kernel<<<dim3(16, 16, 4), dim3(32, 8)>>>(Wq, Wk, Wv, Wo);
    split_f32_kernel<<<512, 1024>>>(x, (__half*)pxh, (__half*)pxl);

    hmma_gemm_kernel<<<dim3(4, 8, 3), 256>>>(
        (const __half*)pxh, (const __half*)pxl,
        (const __half*)pwth, (const __half*)pwtl,
        bq, bk, bv, (float*)pq, (float*)pk, (float*)pv);

    norm_sim_kernel<<<L_, 512>>>(qks);

    prep_split_kernel<<<dim3(32, 16, 2), dim3(32, 8)>>>();
    prep_filters_kernel<<<48, 1024>>>(flt);

    conv_mma_kernel<<<dim3(8, 8, 24), 256>>>();

    zsum_kernel<<<dim3(NCH, H_), 256>>>(Wg, bg, kvs);

    coef_kernel<<<H_, 1024>>>();

    chunk_prefix_kernel<<<dim3(16, H_), 256>>>();

    ctxt_scan_kernel<<<dim3(NCH, H_), 256>>>(kvs);

    split_f32_kernel<<<512, 1024>>>((const float*)pctxt, (__half*)pch, (__half*)pcl);

    hmma_gemm_kernel<<<dim3(4, 8, 1), 256>>>(
        (const __half*)pch, (const __half*)pcl,
        (const __half*)pwth + 3 * (D_ * D_), (const __half*)pwtl + 3 * (D_ * D_),
        bo, bo, bo, out, out, out);
}

// round 14
// speedup vs baseline: 1.0121x; 1.0121x over previous
#include <cuda_runtime.h>
#include <cuda_fp16.h>
#include <math.h>
#include <stdint.h>

#define L_   1024
#define D_   512
#define H_   8
#define HD_  64
#define KF_  24
#define EPSF 1e-5f
#define NCH  32
#define CL   32

// ---------------- static scratch ----------------
__device__ float g_q[L_ * D_];
__device__ float g_k[L_ * D_];
__device__ float g_v[L_ * D_];
__device__ __half g_ckh[(size_t)KF_ * L_ * D_];   // conv(k_norm) fp16: [kf][l][c]
__device__ __half g_cvh[(size_t)KF_ * L_ * D_];   // conv(v_norm) fp16
__device__ float g_sim[H_ * L_];
__device__ float g_gate[H_ * L_];
__device__ float g_coef[H_ * L_];
__device__ float g_ctxt[L_ * D_];
__device__ float g_T[H_][NCH][4096];
__device__ float g_P[H_][NCH][4096];

// fp16 operands
__device__ __half g_uTh[1024 * 1024];            // u, [c (k:0-511, v:512-1023)][t]
__device__ __half g_fpad[2 * KF_ * 2048];        // filters [hi/lo][kf][1023 + lag]
__device__ __half g_xh[L_ * D_], g_xl[L_ * D_];  // x splits [m][k]
__device__ __half g_ch[L_ * D_], g_cl[L_ * D_];  // ctxt splits [m][k]
__device__ __half g_WTh[4 * D_ * D_], g_WTl[4 * D_ * D_]; // W^T splits [mat][n][k]

// ---------------- mma.sync fp16 ----------------
__device__ __forceinline__ void mma16816(float* c, const uint32_t* a, const uint32_t* b) {
    asm volatile(
        "mma.sync.aligned.m16n8k16.row.col.f32.f16.f16.f32 "
        "{%0,%1,%2,%3}, {%4,%5,%6,%7}, {%8,%9}, {%0,%1,%2,%3};"
        : "+f"(c[0]), "+f"(c[1]), "+f"(c[2]), "+f"(c[3])
        : "r"(a[0]), "r"(a[1]), "r"(a[2]), "r"(a[3]), "r"(b[0]), "r"(b[1]));
}

__device__ __forceinline__ void cp_async16(uint32_t saddr, const void* gptr) {
    asm volatile("cp.async.cg.shared.global [%0], [%1], 16;" :: "r"(saddr), "l"(gptr));
}
#define CP_COMMIT() asm volatile("cp.async.commit_group;" ::: "memory")
#define CP_WAIT0()  asm volatile("cp.async.wait_group 0;" ::: "memory")
#define CP_WAIT1()  asm volatile("cp.async.wait_group 1;" ::: "memory")

// ---------------- prep: W transpose + fp16 split ----------------
__global__ void prep_wT_kernel(const float* __restrict__ w0, const float* __restrict__ w1,
                               const float* __restrict__ w2, const float* __restrict__ w3) {
    __shared__ float tile[32][33];
    const int k0 = blockIdx.x * 32, n0 = blockIdx.y * 32, z = blockIdx.z;
    const float* __restrict__ src = (z == 0) ? w0 : (z == 1) ? w1 : (z == 2) ? w2 : w3;
    const int tx = threadIdx.x, ty = threadIdx.y;
    #pragma unroll
    for (int kk = 0; kk < 4; kk++) {
        int i = ty + 8 * kk;
        tile[i][tx] = src[(k0 + i) * 512 + n0 + tx];
    }
    __syncthreads();
    const size_t zb = (size_t)z * (D_ * D_);
    #pragma unroll
    for (int kk = 0; kk < 4; kk++) {
        int i = ty + 8 * kk;
        float v = tile[tx][i];
        __half hi = __float2half_rn(v);
        __half lo = __float2half_rn(v - __half2float(hi));
        size_t idx = zb + (size_t)(n0 + i) * 512 + k0 + tx;
        g_WTh[idx] = hi;
        g_WTl[idx] = lo;
    }
}

// ---------------- prep: elementwise fp32 -> fp16 hi/lo split ----------------
__global__ void split_f32_kernel(const float* __restrict__ src,
                                 __half* __restrict__ dh, __half* __restrict__ dl) {
    int i = blockIdx.x * 1024 + threadIdx.x;
    if (i < L_ * D_) {
        float v = src[i];
        __half hi = __float2half_rn(v);
        dh[i] = hi;
        dl[i] = __float2half_rn(v - __half2float(hi));
    }
}

// ---------------- HMMA projection GEMM ----------------
#define GS 40
__global__ void __launch_bounds__(256) hmma_gemm_kernel(
    const __half* __restrict__ Ah, const __half* __restrict__ Al,
    const __half* __restrict__ WTh, const __half* __restrict__ WTl,
    const float* __restrict__ b0, const float* __restrict__ b1, const float* __restrict__ b2,
    float* C0, float* C1, float* C2) {
    __shared__ __align__(16) __half SA[2][128][GS];
    __shared__ __align__(16) __half SB[2][128][GS];

    const int tid = threadIdx.x;
    const int wid = tid >> 5, lane = tid & 31;
    const int g = lane >> 2, tg = lane & 3;
    const int wm = (wid & 3) * 32, wn = (wid >> 2) * 64;
    const int n0 = blockIdx.x * 128, m0 = blockIdx.y * 128, z = blockIdx.z;

    const __half* __restrict__ Bh = WTh + (size_t)z * (D_ * D_);
    const __half* __restrict__ Bl = WTl + (size_t)z * (D_ * D_);
    const float* __restrict__ bias = (z == 0) ? b0 : (z == 1) ? b1 : b2;
    float* __restrict__ C = (z == 0) ? C0 : (z == 1) ? C1 : C2;

    float acc[2][8][4] = {};

    for (int k0 = 0; k0 < 512; k0 += 32) {
        #pragma unroll
        for (int r = 0; r < 8; r++) {
            int idx = tid + 256 * r;
            int which = idx >> 10;
            int split = (idx >> 9) & 1;
            int rem = idx & 511;
            int row = rem >> 2, qq = rem & 3;
            const __half* src = which
                ? (split ? Bl : Bh) + (size_t)(n0 + row) * 512 + k0 + qq * 8
                : (split ? Al : Ah) + (size_t)(m0 + row) * 512 + k0 + qq * 8;
            __half* dst = which ? &SB[split][row][qq * 8] : &SA[split][row][qq * 8];
            cp_async16((uint32_t)__cvta_generic_to_shared(dst), src);
        }
        CP_COMMIT();
        CP_WAIT0();
        __syncthreads();

        #pragma unroll
        for (int ks = 0; ks < 2; ks++) {
            const int kb = ks * 16 + tg * 2;
            uint32_t ah[2][4], al2[2][4];
            #pragma unroll
            for (int i = 0; i < 2; i++) {
                int r = wm + i * 16 + g;
                ah[i][0] = *(const uint32_t*)&SA[0][r][kb];
                ah[i][1] = *(const uint32_t*)&SA[0][r + 8][kb];
                ah[i][2] = *(const uint32_t*)&SA[0][r][kb + 8];
                ah[i][3] = *(const uint32_t*)&SA[0][r + 8][kb + 8];
                al2[i][0] = *(const uint32_t*)&SA[1][r][kb];
                al2[i][1] = *(const uint32_t*)&SA[1][r + 8][kb];
                al2[i][2] = *(const uint32_t*)&SA[1][r][kb + 8];
                al2[i][3] = *(const uint32_t*)&SA[1][r + 8][kb + 8];
            }
            #pragma unroll
            for (int j = 0; j < 8; j++) {
                int cc = wn + j * 8 + g;
                uint32_t bh[2], bl[2];
                bh[0] = *(const uint32_t*)&SB[0][cc][kb];
                bh[1] = *(const uint32_t*)&SB[0][cc][kb + 8];
                bl[0] = *(const uint32_t*)&SB[1][cc][kb];
                bl[1] = *(const uint32_t*)&SB[1][cc][kb + 8];
                #pragma unroll
                for (int i = 0; i < 2; i++) {
                    mma16816(acc[i][j], ah[i], bh);
                    mma16816(acc[i][j], al2[i], bh);
                    mma16816(acc[i][j], ah[i], bl);
                }
            }
        }
        __syncthreads();
    }

    #pragma unroll
    for (int i = 0; i < 2; i++) {
        int r = m0 + wm + i * 16 + g;
        #pragma unroll
        for (int j = 0; j < 8; j++) {
            int cc = n0 + wn + j * 8 + tg * 2;
            float bv0 = bias[cc], bv1 = bias[cc + 1];
            *(float2*)(C + (size_t)r * 512 + cc) = make_float2(acc[i][j][0] + bv0, acc[i][j][1] + bv1);
            *(float2*)(C + (size_t)(r + 8) * 512 + cc) = make_float2(acc[i][j][2] + bv0, acc[i][j][3] + bv1);
        }
    }
}

// ---------------- sim + in-place L2 norm ----------------
__global__ void norm_sim_kernel(const float* __restrict__ qk_scale) {
    const int l = blockIdx.x;
    const int c = threadIdx.x;
    const int head = c >> 6, d = c & 63;
    float q = g_q[l * 512 + c];
    float k = g_k[l * 512 + c];
    float v = g_v[l * 512 + c];

    __shared__ float sd[512], sk[512], sv[512];
    sd[c] = q * k; sk[c] = k * k; sv[c] = v * v;
    __syncthreads();
    for (int off = 32; off >= 1; off >>= 1) {
        if (d < off) {
            sd[c] += sd[c + off];
            sk[c] += sk[c + off];
            sv[c] += sv[c + off];
        }
        __syncthreads();
    }
    float nk = fmaxf(sqrtf(sk[head * 64]), 1e-12f);
    float nv = fmaxf(sqrtf(sv[head * 64]), 1e-12f);
    g_k[l * 512 + c] = k / nk;
    g_v[l * 512 + c] = v / nv;
    if (d == 0) g_sim[head * L_ + l] = sd[head * 64] * qk_scale[head];
}

// ---------------- prep: transpose + fp16 convert of normalized k,v ----------------
__global__ void prep_split_kernel() {
    __shared__ float tile[32][33];
    const int t0 = blockIdx.x * 32, c0 = blockIdx.y * 32, z = blockIdx.z;
    const float* __restrict__ src = z ? g_v : g_k;
    const int tx = threadIdx.x, ty = threadIdx.y;
    #pragma unroll
    for (int kk = 0; kk < 4; kk++) {
        int i = ty + 8 * kk;
        tile[i][tx] = src[(t0 + i) * 512 + c0 + tx];
    }
    __syncthreads();
    const int rb = z * 512;
    #pragma unroll
    for (int kk = 0; kk < 4; kk++) {
        int i = ty + 8 * kk;
        g_uTh[(size_t)(rb + c0 + i) * 1024 + t0 + tx] = __float2half_rn(tile[tx][i]);
    }
}

// ---------------- prep: padded filters fp16 hi/lo ----------------
__global__ void prep_filters_kernel(const float* __restrict__ flt) {
    int idx = blockIdx.x * 1024 + threadIdx.x;
    if (idx >= KF_ * 2048) return;
    int kf = idx >> 11, d = idx & 2047;
    float v = 0.0f;
    if (d >= 1023 && d < 2047) v = flt[(d - 1023) * KF_ + kf];
    __half hi = __float2half_rn(v);
    __half lo = __float2half_rn(v - __half2float(hi));
    g_fpad[idx] = hi;
    g_fpad[KF_ * 2048 + idx] = lo;
}

// ---------------- HMMA conv (fp16 2-term), triple-buffered, 2 CTAs/SM ----------------
#define BS_STRIDE 40

__global__ void __launch_bounds__(256, 2) conv_mma_kernel() {
    __shared__ __align__(16) __half Bs[3][128][BS_STRIDE];
    __shared__ uint32_t fwp[3][2][160];

    const int tid = threadIdx.x;
    const int wid = tid >> 5, lane = tid & 31;
    const int g = lane >> 2, tg = lane & 3;
    const int wm = (wid & 3) * 32;
    const int wn = (wid >> 2) * 64;

    const int c0 = blockIdx.x * 128;
    const int l0 = (7 - blockIdx.y) * 128;
    const int kf = blockIdx.z;

    const __half* __restrict__ fp_hi = g_fpad + (size_t)kf * 2048;
    const __half* __restrict__ fp_lo = g_fpad + (size_t)(KF_ + kf) * 2048;

    const int nIter = (l0 + 128) >> 5;   // >= 4

    auto prefetch = [&](int it, int buf) {
        const int t0 = it << 5;
        #pragma unroll
        for (int r = 0; r < 2; r++) {
            int cidx = tid + 256 * r;
            int c = cidx >> 2, qq = cidx & 3;
            const __half* gsrc = g_uTh + (size_t)(c0 + c) * 1024 + t0 + qq * 8;
            cp_async16((uint32_t)__cvta_generic_to_shared(&Bs[buf][c][qq * 8]), gsrc);
        }
        CP_COMMIT();
        if (tid < 160) {
            int dmin = 1023 + (l0 - t0) - 31;
            uint32_t h0 = (uint32_t)__half_as_ushort(fp_hi[dmin + tid]);
            uint32_t h1 = (uint32_t)__half_as_ushort(fp_hi[dmin + tid - 1]);
            fwp[buf][0][tid] = h0 | (h1 << 16);
            uint32_t lo0 = (uint32_t)__half_as_ushort(fp_lo[dmin + tid]);
            uint32_t lo1 = (uint32_t)__half_as_ushort(fp_lo[dmin + tid - 1]);
            fwp[buf][1][tid] = lo0 | (lo1 << 16);
        }
    };

    float acc[2][8][4] = {};

    prefetch(0, 0);
    prefetch(1, 1);

    for (int it = 0; it < nIter; it++) {
        const int buf = it % 3;
        // outstanding groups at this point: {it} and {it+1 if issued}
        if (it + 1 < nIter) CP_WAIT1(); else CP_WAIT0();
        __syncthreads();
        if (it + 2 < nIter) prefetch(it + 2, (it + 2) % 3);

        #pragma unroll
        for (int ks = 0; ks < 2; ks++) {
            const int kb = ks * 16;
            uint32_t a0[2][2], a1[2][2], a2[2][2];
            #pragma unroll
            for (int s = 0; s < 2; s++)
                #pragma unroll
                for (int i = 0; i < 2; i++) {
                    int x = wm + i * 16 + g - (kb + tg * 2) + 31;
                    a0[s][i] = fwp[buf][s][x];
                    a1[s][i] = fwp[buf][s][x + 8];
                    a2[s][i] = fwp[buf][s][x - 8];
                }
            #pragma unroll
            for (int j = 0; j < 8; j++) {
                int cc = wn + j * 8 + g;
                uint32_t bh[2];
                bh[0] = *(const uint32_t*)&Bs[buf][cc][kb + tg * 2];
                bh[1] = *(const uint32_t*)&Bs[buf][cc][kb + tg * 2 + 8];
                #pragma unroll
                for (int i = 0; i < 2; i++) {
                    uint32_t ah[4] = {a0[0][i], a1[0][i], a2[0][i], a0[0][i]};
                    uint32_t al[4] = {a0[1][i], a1[1][i], a2[1][i], a0[1][i]};
                    mma16816(acc[i][j], ah, bh);
                    mma16816(acc[i][j], al, bh);
                }
            }
        }
    }

    __half* __restrict__ base = (c0 < 512) ? g_ckh : g_cvh;
    const int cb0 = (c0 < 512) ? c0 : c0 - 512;
    #pragma unroll
    for (int i = 0; i < 2; i++) {
        int r = l0 + wm + i * 16 + g;
        #pragma unroll
        for (int j = 0; j < 8; j++) {
            int cc = cb0 + wn + j * 8 + tg * 2;
            size_t o0 = ((size_t)kf * 1024 + r) * 512 + cc;
            size_t o1 = ((size_t)kf * 1024 + r + 8) * 512 + cc;
            *(__half2*)(base + o0) = __floats2half2_rn(acc[i][j][0], acc[i][j][1]);
            *(__half2*)(base + o1) = __floats2half2_rn(acc[i][j][2], acc[i][j][3]);
        }
    }
}

// ---------------- Pass A: per-chunk gated-Z totals + gates ----------------
// thread mapping: e = tid>>2 (0..63), dg = tid&3 (d-range dg*16..+16)
__global__ void __launch_bounds__(256) zsum_kernel(const float* __restrict__ Wg,
                                                   const float* __restrict__ bg,
                                                   const float* __restrict__ kvscale) {
    const int chunk = blockIdx.x, head = blockIdx.y;
    const int tid = threadIdx.x;
    const int e = tid >> 2, dg = tid & 3;
    const int l0 = chunk * CL;

    __shared__ __align__(16) __half st[2][48][64];
    __shared__ float red[8];

    float scl[16], wg[16];
    #pragma unroll
    for (int r = 0; r < 16; r++) {
        int m = (dg * 16 + r) * 64 + e;
        scl[r] = kvscale[head * 4096 + m];
        wg[r] = Wg[m];
    }
    const float bgv = bg[0];

    auto stage = [&](int l, int buf) {
        for (int i = tid; i < 384; i += 256) {
            int row = i >> 3, ch = i & 7;
            const __half* src = ((row < 24) ? (g_ckh + (size_t)row * (L_ * D_))
                                            : (g_cvh + (size_t)(row - 24) * (L_ * D_)))
                                + (size_t)l * 512 + head * 64 + ch * 8;
            cp_async16((uint32_t)__cvta_generic_to_shared(&st[buf][row][ch * 8]), src);
        }
        CP_COMMIT();
    };

    float S[16] = {};
    stage(l0, 0);

    for (int li = 0; li < CL; li++) {
        const int buf = li & 1;
        CP_WAIT0();
        __syncthreads();
        if (li + 1 < CL) stage(l0 + li + 1, buf ^ 1);

        float z[16] = {};
        #pragma unroll
        for (int kf = 0; kf < KF_; kf++) {
            float ktv = __half2float(st[buf][kf][e]);
            const __half2* vp = (const __half2*)&st[buf][24 + kf][dg * 16];
            float2 p0 = __half22float2(vp[0]), p1 = __half22float2(vp[1]);
            float2 p2 = __half22float2(vp[2]), p3 = __half22float2(vp[3]);
            float2 p4 = __half22float2(vp[4]), p5 = __half22float2(vp[5]);
            float2 p6 = __half22float2(vp[6]), p7 = __half22float2(vp[7]);
            z[0] += p0.x * ktv;  z[1] += p0.y * ktv;  z[2] += p1.x * ktv;  z[3] += p1.y * ktv;
            z[4] += p2.x * ktv;  z[5] += p2.y * ktv;  z[6] += p3.x * ktv;  z[7] += p3.y * ktv;
            z[8] += p4.x * ktv;  z[9] += p4.y * ktv;  z[10] += p5.x * ktv; z[11] += p5.y * ktv;
            z[12] += p6.x * ktv; z[13] += p6.y * ktv; z[14] += p7.x * ktv; z[15] += p7.y * ktv;
        }
        float lp = 0.0f;
        #pragma unroll
        for (int r = 0; r < 16; r++) {
            z[r] *= scl[r];
            lp += z[r] * wg[r];
        }
        #pragma unroll
        for (int off = 16; off >= 1; off >>= 1)
            lp += __shfl_xor_sync(0xffffffffu, lp, off);
        if ((tid & 31) == 0) red[tid >> 5] = lp;
        __syncthreads();
        float s = red[0] + red[1] + red[2] + red[3] + red[4] + red[5] + red[6] + red[7];
        float rl = fmaxf(s + bgv, 0.0f);
        float gate = rl * rl + EPSF;
        if (tid == 0) g_gate[head * L_ + l0 + li] = gate;
        #pragma unroll
        for (int r = 0; r < 16; r++) S[r] += gate * z[r];
    }

    #pragma unroll
    for (int r = 0; r < 16; r++)
        g_T[head][chunk][(dg * 16 + r) * 64 + e] = S[r];
}

// ---------------- Pass B: exclusive chunk prefix ----------------
__global__ void chunk_prefix_kernel() {
    const int head = blockIdx.y;
    const int comp = blockIdx.x * 256 + threadIdx.x;
    float run = 0.0f;
    #pragma unroll
    for (int ch = 0; ch < NCH; ch++) {
        float t = g_T[head][ch][comp];
        g_P[head][ch][comp] = run;
        run += t;
    }
}

// ---------------- coef: online softmax scan + gate cumsum ----------------
__global__ void coef_kernel() {
    const int head = blockIdx.x;
    const int i = threadIdx.x;
    __shared__ float sm[1024], ss[1024], sg[1024];
    float si = g_sim[head * L_ + i];
    sm[i] = si; ss[i] = 1.0f; sg[i] = g_gate[head * L_ + i];
    __syncthreads();
    for (int off = 1; off < 1024; off <<= 1) {
        float mp = 0.f, sp = 0.f, gp = 0.f;
        bool has = (i >= off);
        if (has) { mp = sm[i - off]; sp = ss[i - off]; gp = sg[i - off]; }
        __syncthreads();
        if (has) {
            float mi = sm[i], s_i = ss[i];
            float mn = fmaxf(mp, mi);
            ss[i] = sp * __expf(mp - mn) + s_i * __expf(mi - mn);
            sm[i] = mn;
            sg[i] += gp;
        }
        __syncthreads();
    }
    float w = __expf(si - sm[i]) / (ss[i] + EPSF);
    float silu = w / (1.0f + __expf(-w));
    g_coef[head * L_ + i] = (1.0f + silu) / (sg[i] + EPSF);
}

// ---------------- Pass C: running scan + q contraction -> ctxt ----------------
// thread mapping: e = tid>>2, dg = tid&3; dg-reduction via shfl (1 barrier per l)
__global__ void __launch_bounds__(256) ctxt_scan_kernel(const float* __restrict__ kvscale) {
    const int chunk = blockIdx.x, head = blockIdx.y;
    const int tid = threadIdx.x;
    const int e = tid >> 2, dg = tid & 3;
    const int l0 = chunk * CL;

    __shared__ __align__(16) __half st[2][48][64];
    __shared__ __align__(16) float sq[2][64];
    __shared__ float gt[CL], cf[CL];

    float scl[16];
    #pragma unroll
    for (int r = 0; r < 16; r++)
        scl[r] = kvscale[head * 4096 + (dg * 16 + r) * 64 + e];

    if (tid < CL) {
        gt[tid] = g_gate[head * L_ + l0 + tid];
        cf[tid] = g_coef[head * L_ + l0 + tid];
    }

    float S[16];
    #pragma unroll
    for (int r = 0; r < 16; r++)
        S[r] = g_P[head][chunk][(dg * 16 + r) * 64 + e];

    auto stage = [&](int l, int buf) {
        for (int i = tid; i < 400; i += 256) {
            if (i < 384) {
                int row = i >> 3, ch = i & 7;
                const __half* src = ((row < 24) ? (g_ckh + (size_t)row * (L_ * D_))
                                                : (g_cvh + (size_t)(row - 24) * (L_ * D_)))
                                    + (size_t)l * 512 + head * 64 + ch * 8;
                cp_async16((uint32_t)__cvta_generic_to_shared(&st[buf][row][ch * 8]), src);
            } else {
                int qi = i - 384;
                const float* src = g_q + (size_t)l * 512 + head * 64 + qi * 4;
                cp_async16((uint32_t)__cvta_generic_to_shared(&sq[buf][qi * 4]), src);
            }
        }
        CP_COMMIT();
    };

    stage(l0, 0);

    for (int li = 0; li < CL; li++) {
        const int buf = li & 1;
        CP_WAIT0();
        __syncthreads();
        if (li + 1 < CL) stage(l0 + li + 1, buf ^ 1);

        float z[16] = {};
        #pragma unroll
        for (int kf = 0; kf < KF_; kf++) {
            float ktv = __half2float(st[buf][kf][e]);
            const __half2* vp = (const __half2*)&st[buf][24 + kf][dg * 16];
            float2 p0 = __half22float2(vp[0]), p1 = __half22float2(vp[1]);
            float2 p2 = __half22float2(vp[2]), p3 = __half22float2(vp[3]);
            float2 p4 = __half22float2(vp[4]), p5 = __half22float2(vp[5]);
            float2 p6 = __half22float2(vp[6]), p7 = __half22float2(vp[7]);
            z[0] += p0.x * ktv;  z[1] += p0.y * ktv;  z[2] += p1.x * ktv;  z[3] += p1.y * ktv;
            z[4] += p2.x * ktv;  z[5] += p2.y * ktv;  z[6] += p3.x * ktv;  z[7] += p3.y * ktv;
            z[8] += p4.x * ktv;  z[9] += p4.y * ktv;  z[10] += p5.x * ktv; z[11] += p5.y * ktv;
            z[12] += p6.x * ktv; z[13] += p6.y * ktv; z[14] += p7.x * ktv; z[15] += p7.y * ktv;
        }
        const float gate = gt[li];
        #pragma unroll
        for (int r = 0; r < 16; r++) S[r] += gate * scl[r] * z[r];

        const float4* qp = (const float4*)&sq[buf][dg * 16];
        float4 q0 = qp[0], q1 = qp[1], q2 = qp[2], q3 = qp[3];
        float part =
            q0.x * S[0]  + q0.y * S[1]  + q0.z * S[2]  + q0.w * S[3] +
            q1.x * S[4]  + q1.y * S[5]  + q1.z * S[6]  + q1.w * S[7] +
            q2.x * S[8]  + q2.y * S[9]  + q2.z * S[10] + q2.w * S[11] +
            q3.x * S[12] + q3.y * S[13] + q3.z * S[14] + q3.w * S[15];
        part += __shfl_xor_sync(0xffffffffu, part, 1);
        part += __shfl_xor_sync(0xffffffffu, part, 2);
        if (dg == 0)
            g_ctxt[(size_t)(l0 + li) * 512 + head * 64 + e] = part * cf[li];
    }
}

// ---------------- launch ----------------
extern "C" void kernel_launch(void* const* d_in, const int* in_sizes, int n_in,
                              void* d_out, int out_size) {
    const float* x   = (const float*)d_in[0];
    const float* Wq  = (const float*)d_in[1];
    const float* bq  = (const float*)d_in[2];
    const float* Wk  = (const float*)d_in[3];
    const float* bk  = (const float*)d_in[4];
    const float* Wv  = (const float*)d_in[5];
    const float* bv  = (const float*)d_in[6];
    const float* Wo  = (const float*)d_in[7];
    const float* bo  = (const float*)d_in[8];
    const float* Wg  = (const float*)d_in[9];
    const float* bg  = (const float*)d_in[10];
    const float* kvs = (const float*)d_in[11];
    const float* qks = (const float*)d_in[12];
    const float* flt = (const float*)d_in[13];
    float* out = (float*)d_out;

    void *pq, *pk, *pv, *pctxt, *pxh, *pxl, *pch, *pcl, *pwth, *pwtl;
    cudaGetSymbolAddress(&pq, g_q);
    cudaGetSymbolAddress(&pk, g_k);
    cudaGetSymbolAddress(&pv, g_v);
    cudaGetSymbolAddress(&pctxt, g_ctxt);
    cudaGetSymbolAddress(&pxh, g_xh);
    cudaGetSymbolAddress(&pxl, g_xl);
    cudaGetSymbolAddress(&pch, g_ch);
    cudaGetSymbolAddress(&pcl, g_cl);
    cudaGetSymbolAddress(&pwth, g_WTh);
    cudaGetSymbolAddress(&pwtl, g_WTl);

    prep_wT_kernel<<<dim3(16, 16, 4), dim3(32, 8)>>>(Wq, Wk, Wv, Wo);
    split_f32_kernel<<<512, 1024>>>(x, (__half*)pxh, (__half*)pxl);

    hmma_gemm_kernel<<<dim3(4, 8, 3), 256>>>(
        (const __half*)pxh, (const __half*)pxl,
        (const __half*)pwth, (const __half*)pwtl,
        bq, bk, bv, (float*)pq, (float*)pk, (float*)pv);

    norm_sim_kernel<<<L_, 512>>>(qks);

    prep_split_kernel<<<dim3(32, 16, 2), dim3(32, 8)>>>();
    prep_filters_kernel<<<48, 1024>>>(flt);

    conv_mma_kernel<<<dim3(8, 8, 24), 256>>>();

    zsum_kernel<<<dim3(NCH, H_), 256>>>(Wg, bg, kvs);

    coef_kernel<<<H_, 1024>>>();

    chunk_prefix_kernel<<<dim3(16, H_), 256>>>();

    ctxt_scan_kernel<<<dim3(NCH, H_), 256>>>(kvs);

    split_f32_kernel<<<512, 1024>>>((const float*)pctxt, (__half*)pch, (__half*)pcl);

    hmma_gemm_kernel<<<dim3(4, 8, 1), 256>>>(
        (const __half*)pch, (const __half*)pcl,
        (const __half*)pwth + 3 * (D_ * D_), (const __half*)pwtl + 3 * (D_ * D_),
        bo, bo, bo, out, out, out);
}